// round 2
// baseline (speedup 1.0000x reference)
#include <cuda_runtime.h>

// Problem constants
#define BB   256          // batch
#define II   512          // input dim
#define RR   1024         // hidden dim
#define UU   11           // unroll steps
#define NOUT 4096         // 4*RR gate width

// ---------------- scratch state (no allocation allowed) ----------------
__device__ __align__(16) float g_pre0[BB * NOUT];   // 4 MB
__device__ __align__(16) float g_pre1[BB * NOUT];   // 4 MB
__device__ __align__(16) float g_h0[BB * RR];
__device__ __align__(16) float g_c0[BB * RR];
__device__ __align__(16) float g_h1[BB * RR];
__device__ __align__(16) float g_c1[BB * RR];

// ---------------- init: unpack (B, 2L=4, R) states ----------------
__global__ void init_states_kernel(const float* __restrict__ st) {
    int idx = blockIdx.x * blockDim.x + threadIdx.x;
    if (idx >= BB * RR) return;
    int b = idx / RR, r = idx % RR;
    const float* p = st + (size_t)b * 4 * RR + r;
    g_h0[idx] = p[0 * RR];
    g_c0[idx] = p[1 * RR];
    g_h1[idx] = p[2 * RR];
    g_c1[idx] = p[3 * RR];
}

// ---------------- fused dual GEMM: C = A1@W1^T + A2@W2^T + b1 + b2 ----------------
// C: (256 x 4096), A row-major (256 x K), W row-major (4096 x K) -> TN gemm,
// both operands K-contiguous. Tiles: BM=64, BN=64, BK=16, 256 threads, 4x4/thread.
#define BM 64
#define BN 64
#define BK 16

__global__ __launch_bounds__(256, 2) void gemm2_kernel(
    const float* __restrict__ A1, const float* __restrict__ W1, int K1,
    const float* __restrict__ A2, const float* __restrict__ W2, int K2,
    const float* __restrict__ b1, const float* __restrict__ b2,
    float* __restrict__ C)
{
    __shared__ __align__(16) float As[BK][BM + 4];  // k-major, padded
    __shared__ __align__(16) float Bs[BK][BN + 4];

    const int tx = threadIdx.x & 15;   // N micro index (16)
    const int ty = threadIdx.x >> 4;   // M micro index (16)
    const int m0 = blockIdx.y * BM;
    const int n0 = blockIdx.x * BN;
    const int lr = threadIdx.x >> 2;   // 0..63  (row of tile to load)
    const int lc = threadIdx.x & 3;    // 0..3   (which float4 in the 16-wide k slab)

    float acc[4][4];
#pragma unroll
    for (int i = 0; i < 4; i++)
#pragma unroll
        for (int j = 0; j < 4; j++) acc[i][j] = 0.f;

    // operand 1 (K1 slabs), then operand 2 (K2 slabs) — no per-iter branch
    const float* Aops[2] = {A1, A2};
    const float* Wops[2] = {W1, W2};
    const int    Kops[2] = {K1, K2};

#pragma unroll
    for (int op = 0; op < 2; op++) {
        const float* __restrict__ A = Aops[op];
        const float* __restrict__ W = Wops[op];
        const int K = Kops[op];
        const float* pa = A + (size_t)(m0 + lr) * K + lc * 4;
        const float* pw = W + (size_t)(n0 + lr) * K + lc * 4;
        for (int k = 0; k < K; k += BK) {
            float4 va = *(const float4*)(pa + k);
            float4 vw = *(const float4*)(pw + k);
            As[lc * 4 + 0][lr] = va.x; As[lc * 4 + 1][lr] = va.y;
            As[lc * 4 + 2][lr] = va.z; As[lc * 4 + 3][lr] = va.w;
            Bs[lc * 4 + 0][lr] = vw.x; Bs[lc * 4 + 1][lr] = vw.y;
            Bs[lc * 4 + 2][lr] = vw.z; Bs[lc * 4 + 3][lr] = vw.w;
            __syncthreads();

#pragma unroll
            for (int kk = 0; kk < BK; kk++) {
                float a[4], b[4];
                *(float4*)a = *(const float4*)&As[kk][ty * 4];
                *(float4*)b = *(const float4*)&Bs[kk][tx * 4];
#pragma unroll
                for (int i = 0; i < 4; i++)
#pragma unroll
                    for (int j = 0; j < 4; j++)
                        acc[i][j] = fmaf(a[i], b[j], acc[i][j]);
            }
            __syncthreads();
        }
    }

#pragma unroll
    for (int j = 0; j < 4; j++) {
        int n = n0 + tx * 4 + j;
        float bias = b1[n] + b2[n];
#pragma unroll
        for (int i = 0; i < 4; i++) {
            int m = m0 + ty * 4 + i;
            C[(size_t)m * NOUT + n] = acc[i][j] + bias;
        }
    }
}

// ---------------- LSTM cell nonlinearity ----------------
__device__ __forceinline__ float sigm(float x) { return 1.f / (1.f + __expf(-x)); }

__global__ void cell0_kernel() {
    int idx = blockIdx.x * blockDim.x + threadIdx.x;
    int b = idx / RR, r = idx % RR;
    const float* pre = g_pre0 + (size_t)b * NOUT;
    float gi = pre[r];
    float gf = pre[RR + r];
    float go = pre[2 * RR + r];
    float gg = pre[3 * RR + r];
    float c = sigm(gf) * g_c0[idx] + sigm(gi) * tanhf(gg);
    g_c0[idx] = c;
    g_h0[idx] = sigm(go) * tanhf(c);
}

__global__ void cell1_kernel(float* __restrict__ out, int u) {
    int idx = blockIdx.x * blockDim.x + threadIdx.x;
    int b = idx / RR, r = idx % RR;
    // ys[u] = h1 BEFORE this step's update
    out[(size_t)b * (UU * RR) + (size_t)u * RR + r] = g_h1[idx];
    const float* pre = g_pre1 + (size_t)b * NOUT;
    float gi = pre[r];
    float gf = pre[RR + r];
    float go = pre[2 * RR + r];
    float gg = pre[3 * RR + r];
    float c = sigm(gf) * g_c1[idx] + sigm(gi) * tanhf(gg);
    g_c1[idx] = c;
    g_h1[idx] = sigm(go) * tanhf(c);
}

// ---------------- launch ----------------
extern "C" void kernel_launch(void* const* d_in, const int* in_sizes, int n_in,
                              void* d_out, int out_size) {
    const float* x   = (const float*)d_in[0];
    const float* st  = (const float*)d_in[1];
    const float* Wi0 = (const float*)d_in[2];
    const float* bi0 = (const float*)d_in[3];
    const float* Wh0 = (const float*)d_in[4];
    const float* bh0 = (const float*)d_in[5];
    const float* Wi1 = (const float*)d_in[6];
    const float* bi1 = (const float*)d_in[7];
    const float* Wh1 = (const float*)d_in[8];
    const float* bh1 = (const float*)d_in[9];
    float* out = (float*)d_out;

    void* p;
    float *pre0, *pre1, *h0, *h1;
    cudaGetSymbolAddress(&p, g_pre0); pre0 = (float*)p;
    cudaGetSymbolAddress(&p, g_pre1); pre1 = (float*)p;
    cudaGetSymbolAddress(&p, g_h0);   h0   = (float*)p;
    cudaGetSymbolAddress(&p, g_h1);   h1   = (float*)p;

    const dim3 gg(NOUT / BN, BB / BM);   // (64, 4) = 256 CTAs
    const int cell_blocks = (BB * RR) / 256;

    init_states_kernel<<<(BB * RR + 255) / 256, 256>>>(st);

    for (int u = 0; u < UU; u++) {
        // layer 0: pre0 = x@Wi0[u]^T + h0@Wh0[u]^T + bi0[u] + bh0[u]
        gemm2_kernel<<<gg, 256>>>(
            x,  Wi0 + (size_t)u * NOUT * II, II,
            h0, Wh0 + (size_t)u * NOUT * RR, RR,
            bi0 + (size_t)u * NOUT, bh0 + (size_t)u * NOUT, pre0);
        cell0_kernel<<<cell_blocks, 256>>>();

        // layer 1: pre1 = h0_new@Wi1[u]^T + h1@Wh1[u]^T + bi1[u] + bh1[u]
        gemm2_kernel<<<gg, 256>>>(
            h0, Wi1 + (size_t)u * NOUT * RR, RR,
            h1, Wh1 + (size_t)u * NOUT * RR, RR,
            bi1 + (size_t)u * NOUT, bh1 + (size_t)u * NOUT, pre1);
        cell1_kernel<<<cell_blocks, 256>>>(out, u);
    }
}

// round 4
// speedup vs baseline: 2.5804x; 2.5804x over previous
#include <cuda_runtime.h>
#include <cuda_bf16.h>
#include <cstdint>

#define BB   256
#define II   512
#define RR   1024
#define UU   11
#define NOUT 4096
#define BN   64
#define BK   32
#define LDB  80      // padded smem row stride in bytes (40 bf16)

// stage layout (bytes): Ahi 256*80, Alo 256*80, Whi 64*80, Wlo 64*80
#define AHI   0
#define ALO   20480
#define WHI   40960
#define WLO   46080
#define STAGE 51200
#define SMEM_TOTAL (2 * STAGE)   // 102400

// ---------------- scratch (static; no allocation) ----------------
__device__ __align__(16) float g_pre0[2 * BB * NOUT];
__device__ __align__(16) float g_pre1[2 * BB * NOUT];
__device__ __align__(16) __nv_bfloat16 g_xhi[BB * II], g_xlo[BB * II];
__device__ __align__(16) __nv_bfloat16 g_h0hi[BB * RR], g_h0lo[BB * RR];
__device__ __align__(16) __nv_bfloat16 g_h1hi[BB * RR], g_h1lo[BB * RR];
__device__ __align__(16) float g_h1[BB * RR];
__device__ __align__(16) float g_c0[BB * RR], g_c1[BB * RR];

static __device__ __forceinline__ uint32_t s2u(const void* p) {
    uint32_t a;
    asm("{ .reg .u64 t; cvta.to.shared.u64 t, %1; cvt.u32.u64 %0, t; }" : "=r"(a) : "l"(p));
    return a;
}
static __device__ __forceinline__ void cpa16(uint32_t s, const void* g) {
    asm volatile("cp.async.cg.shared.global [%0], [%1], 16;" :: "r"(s), "l"(g));
}
static __device__ __forceinline__ void ldsm4(uint32_t* r, uint32_t a) {
    asm volatile("ldmatrix.sync.aligned.m8n8.x4.shared.b16 {%0,%1,%2,%3}, [%4];"
                 : "=r"(r[0]), "=r"(r[1]), "=r"(r[2]), "=r"(r[3]) : "r"(a));
}
static __device__ __forceinline__ void mma16816(float* c, const uint32_t* a, const uint32_t* b) {
    asm volatile(
        "mma.sync.aligned.m16n8k16.row.col.f32.bf16.bf16.f32 "
        "{%0,%1,%2,%3}, {%4,%5,%6,%7}, {%8,%9}, {%0,%1,%2,%3};"
        : "+f"(c[0]), "+f"(c[1]), "+f"(c[2]), "+f"(c[3])
        : "r"(a[0]), "r"(a[1]), "r"(a[2]), "r"(a[3]), "r"(b[0]), "r"(b[1]));
}

// ---------------- 3-pass bf16 HMMA partial GEMM ----------------
// C_part[op] (256 x 4096) = A_op (256 x K) @ W_op (4096 x K)^T, fp32 accum.
// A as bf16 hi/lo planes; W fp32 split on the fly.
__global__ __launch_bounds__(256, 1) void gemm_tc(
    const __nv_bfloat16* __restrict__ a0hi, const __nv_bfloat16* __restrict__ a0lo,
    int K0, const float* __restrict__ W0,
    const __nv_bfloat16* __restrict__ a1hi, const __nv_bfloat16* __restrict__ a1lo,
    int K1, const float* __restrict__ W1,
    float* __restrict__ C)
{
    extern __shared__ __align__(128) char sm[];
    const int tid = threadIdx.x, lane = tid & 31, wid = tid >> 5;
    const int wm = wid & 3, wn = wid >> 2;           // warp grid 4(m) x 2(n)
    const uint32_t sb = s2u(sm);

    const int op = blockIdx.y;
    const __nv_bfloat16* __restrict__ ahi = op ? a1hi : a0hi;
    const __nv_bfloat16* __restrict__ alo = op ? a1lo : a0lo;
    const float* __restrict__ W = op ? W1 : W0;
    const int K = op ? K1 : K0;
    C += (size_t)op * BB * NOUT;
    const int n0 = blockIdx.x * BN;

    float acc[4][4][4];
#pragma unroll
    for (int i = 0; i < 4; i++)
#pragma unroll
        for (int j = 0; j < 4; j++)
#pragma unroll
            for (int q = 0; q < 4; q++) acc[i][j][q] = 0.f;

    const int nch = K / BK;

    // ---- prologue: A chunk 0 via cp.async, W chunk 0 to regs ----
    {
        const int seg = tid & 3, rbase = tid >> 2;
#pragma unroll
        for (int p = 0; p < 4; p++) {
            const int r = p * 64 + rbase;
            const size_t g = (size_t)r * K + seg * 8;
            const uint32_t so = r * LDB + seg * 16;
            cpa16(sb + AHI + so, ahi + g);
            cpa16(sb + ALO + so, alo + g);
        }
        asm volatile("cp.async.commit_group;" ::: "memory");
    }
    float4 wreg[2];
    {
#pragma unroll
        for (int p = 0; p < 2; p++) {
            const int idx = p * 256 + tid, r = idx >> 3, f = idx & 7;
            wreg[p] = *(const float4*)(W + (size_t)(n0 + r) * K + f * 4);
        }
    }

    for (int c = 0; c < nch; c++) {
        const uint32_t base = sb + (c & 1) * STAGE;
        char* bp = sm + (c & 1) * STAGE;

        // ---- STS W(c): split fp32 -> bf16 hi/lo planes ----
#pragma unroll
        for (int p = 0; p < 2; p++) {
            const int idx = p * 256 + tid, r = idx >> 3, f = idx & 7;
            const float4 w = wreg[p];
            const __nv_bfloat16 h0 = __float2bfloat16(w.x), h1 = __float2bfloat16(w.y);
            const __nv_bfloat16 h2 = __float2bfloat16(w.z), h3 = __float2bfloat16(w.w);
            const __nv_bfloat16 l0 = __float2bfloat16(w.x - __bfloat162float(h0));
            const __nv_bfloat16 l1 = __float2bfloat16(w.y - __bfloat162float(h1));
            const __nv_bfloat16 l2 = __float2bfloat16(w.z - __bfloat162float(h2));
            const __nv_bfloat16 l3 = __float2bfloat16(w.w - __bfloat162float(h3));
            __nv_bfloat162 a01 = __halves2bfloat162(h0, h1), a23 = __halves2bfloat162(h2, h3);
            __nv_bfloat162 b01 = __halves2bfloat162(l0, l1), b23 = __halves2bfloat162(l2, l3);
            uint2 uh, ul;
            uh.x = *(uint32_t*)&a01; uh.y = *(uint32_t*)&a23;
            ul.x = *(uint32_t*)&b01; ul.y = *(uint32_t*)&b23;
            *(uint2*)(bp + WHI + r * LDB + f * 8) = uh;
            *(uint2*)(bp + WLO + r * LDB + f * 8) = ul;
        }

        // ---- issue A(c+1) cp.async into other stage ----
        if (c + 1 < nch) {
            const uint32_t nb = sb + ((c + 1) & 1) * STAGE;
            const int seg = tid & 3, rbase = tid >> 2;
#pragma unroll
            for (int p = 0; p < 4; p++) {
                const int r = p * 64 + rbase;
                const size_t g = (size_t)r * K + (c + 1) * BK + seg * 8;
                const uint32_t so = r * LDB + seg * 16;
                cpa16(nb + AHI + so, ahi + g);
                cpa16(nb + ALO + so, alo + g);
            }
            asm volatile("cp.async.commit_group;" ::: "memory");
            asm volatile("cp.async.wait_group 1;" ::: "memory");
        } else {
            asm volatile("cp.async.wait_group 0;" ::: "memory");
        }
        __syncthreads();

        // ---- compute chunk c ----
#pragma unroll
        for (int kk = 0; kk < 2; kk++) {
            const int ar = (lane & 7) + ((lane >> 3) & 1) * 8;
            const int ac = kk * 16 + (lane >> 4) * 8;
            uint32_t ah[4][4], al[4][4];
#pragma unroll
            for (int i = 0; i < 4; i++) {
                const int row = wm * 64 + i * 16 + ar;
                ldsm4(ah[i], base + AHI + row * LDB + ac * 2);
                ldsm4(al[i], base + ALO + row * LDB + ac * 2);
            }
            const int br = (lane & 7) + (lane >> 4) * 8;
            const int bc = kk * 16 + ((lane >> 3) & 1) * 8;
            uint32_t wh[8], wl[8];
#pragma unroll
            for (int j2 = 0; j2 < 2; j2++) {
                const int row = wn * 32 + j2 * 16 + br;
                ldsm4(wh + j2 * 4, base + WHI + row * LDB + bc * 2);
                ldsm4(wl + j2 * 4, base + WLO + row * LDB + bc * 2);
            }
#pragma unroll
            for (int i = 0; i < 4; i++)
#pragma unroll
                for (int j = 0; j < 4; j++) {
                    const uint32_t* bh = &wh[(j >> 1) * 4 + (j & 1) * 2];
                    const uint32_t* bl = &wl[(j >> 1) * 4 + (j & 1) * 2];
                    mma16816(acc[i][j], ah[i], bh);
                    mma16816(acc[i][j], ah[i], bl);
                    mma16816(acc[i][j], al[i], bh);
                }
        }

        // ---- prefetch W(c+1) into regs (latency hidden by sync+next STS) ----
        if (c + 1 < nch) {
#pragma unroll
            for (int p = 0; p < 2; p++) {
                const int idx = p * 256 + tid, r = idx >> 3, f = idx & 7;
                wreg[p] = *(const float4*)(W + (size_t)(n0 + r) * K + (c + 1) * BK + f * 4);
            }
        }
        __syncthreads();
    }

    // ---- epilogue ----
#pragma unroll
    for (int i = 0; i < 4; i++) {
        const int m = wm * 64 + i * 16 + (lane >> 2);
#pragma unroll
        for (int j = 0; j < 4; j++) {
            const int col = n0 + wn * 32 + j * 8 + (lane & 3) * 2;
            float2 v0 = { acc[i][j][0], acc[i][j][1] };
            float2 v1 = { acc[i][j][2], acc[i][j][3] };
            *(float2*)&C[(size_t)m * NOUT + col] = v0;
            *(float2*)&C[(size_t)(m + 8) * NOUT + col] = v1;
        }
    }
}

// ---------------- elementwise kernels ----------------
static __device__ __forceinline__ float sigm(float x) { return 1.f / (1.f + __expf(-x)); }
static __device__ __forceinline__ void split_bf16(float v, __nv_bfloat16* hi, __nv_bfloat16* lo) {
    __nv_bfloat16 h = __float2bfloat16(v);
    *hi = h;
    *lo = __float2bfloat16(v - __bfloat162float(h));
}

__global__ void convert_x_k(const float* __restrict__ x) {
    int idx = blockIdx.x * blockDim.x + threadIdx.x;
    if (idx >= BB * II) return;
    split_bf16(x[idx], &g_xhi[idx], &g_xlo[idx]);
}

__global__ void init_states_k(const float* __restrict__ st) {
    int idx = blockIdx.x * blockDim.x + threadIdx.x;
    if (idx >= BB * RR) return;
    int b = idx >> 10, r = idx & 1023;
    const float* p = st + (size_t)b * 4 * RR + r;
    split_bf16(p[0 * RR], &g_h0hi[idx], &g_h0lo[idx]);
    g_c0[idx] = p[1 * RR];
    float h1 = p[2 * RR];
    g_h1[idx] = h1;
    split_bf16(h1, &g_h1hi[idx], &g_h1lo[idx]);
    g_c1[idx] = p[3 * RR];
}

__global__ void cell0_k(const float* __restrict__ bi, const float* __restrict__ bh) {
    int idx = blockIdx.x * blockDim.x + threadIdx.x;
    int b = idx >> 10, r = idx & 1023;
    const float* p0 = g_pre0 + (size_t)b * NOUT;
    const float* p1 = g_pre0 + (size_t)BB * NOUT + (size_t)b * NOUT;
    float gi = p0[r]          + p1[r]          + bi[r]          + bh[r];
    float gf = p0[RR + r]     + p1[RR + r]     + bi[RR + r]     + bh[RR + r];
    float go = p0[2 * RR + r] + p1[2 * RR + r] + bi[2 * RR + r] + bh[2 * RR + r];
    float gg = p0[3 * RR + r] + p1[3 * RR + r] + bi[3 * RR + r] + bh[3 * RR + r];
    float c = sigm(gf) * g_c0[idx] + sigm(gi) * tanhf(gg);
    g_c0[idx] = c;
    float h = sigm(go) * tanhf(c);
    split_bf16(h, &g_h0hi[idx], &g_h0lo[idx]);
}

__global__ void cell1_k(const float* __restrict__ bi, const float* __restrict__ bh,
                        float* __restrict__ out, int u) {
    int idx = blockIdx.x * blockDim.x + threadIdx.x;
    int b = idx >> 10, r = idx & 1023;
    // ys[u] = h1 BEFORE this step's update
    out[(size_t)b * (UU * RR) + (size_t)u * RR + r] = g_h1[idx];
    const float* p0 = g_pre1 + (size_t)b * NOUT;
    const float* p1 = g_pre1 + (size_t)BB * NOUT + (size_t)b * NOUT;
    float gi = p0[r]          + p1[r]          + bi[r]          + bh[r];
    float gf = p0[RR + r]     + p1[RR + r]     + bi[RR + r]     + bh[RR + r];
    float go = p0[2 * RR + r] + p1[2 * RR + r] + bi[2 * RR + r] + bh[2 * RR + r];
    float gg = p0[3 * RR + r] + p1[3 * RR + r] + bi[3 * RR + r] + bh[3 * RR + r];
    float c = sigm(gf) * g_c1[idx] + sigm(gi) * tanhf(gg);
    g_c1[idx] = c;
    float h = sigm(go) * tanhf(c);
    g_h1[idx] = h;
    split_bf16(h, &g_h1hi[idx], &g_h1lo[idx]);
}

// ---------------- launch ----------------
extern "C" void kernel_launch(void* const* d_in, const int* in_sizes, int n_in,
                              void* d_out, int out_size) {
    const float* x   = (const float*)d_in[0];
    const float* st  = (const float*)d_in[1];
    const float* Wi0 = (const float*)d_in[2];
    const float* bi0 = (const float*)d_in[3];
    const float* Wh0 = (const float*)d_in[4];
    const float* bh0 = (const float*)d_in[5];
    const float* Wi1 = (const float*)d_in[6];
    const float* bi1 = (const float*)d_in[7];
    const float* Wh1 = (const float*)d_in[8];
    const float* bh1 = (const float*)d_in[9];
    float* out = (float*)d_out;

    cudaFuncSetAttribute(gemm_tc, cudaFuncAttributeMaxDynamicSharedMemorySize, SMEM_TOTAL);

    void* p;
    float *pre0, *pre1;
    __nv_bfloat16 *xhi, *xlo, *h0hi, *h0lo, *h1hi, *h1lo;
    cudaGetSymbolAddress(&p, g_pre0); pre0 = (float*)p;
    cudaGetSymbolAddress(&p, g_pre1); pre1 = (float*)p;
    cudaGetSymbolAddress(&p, g_xhi);  xhi  = (__nv_bfloat16*)p;
    cudaGetSymbolAddress(&p, g_xlo);  xlo  = (__nv_bfloat16*)p;
    cudaGetSymbolAddress(&p, g_h0hi); h0hi = (__nv_bfloat16*)p;
    cudaGetSymbolAddress(&p, g_h0lo); h0lo = (__nv_bfloat16*)p;
    cudaGetSymbolAddress(&p, g_h1hi); h1hi = (__nv_bfloat16*)p;
    cudaGetSymbolAddress(&p, g_h1lo); h1lo = (__nv_bfloat16*)p;

    convert_x_k<<<(BB * II + 255) / 256, 256>>>(x);
    init_states_k<<<(BB * RR + 255) / 256, 256>>>(st);

    const dim3 gg(NOUT / BN, 2);        // 64 N-tiles x 2 operand-split
    const int cell_blocks = (BB * RR) / 256;

    for (int u = 0; u < UU; u++) {
        gemm_tc<<<gg, 256, SMEM_TOTAL>>>(
            xhi,  xlo,  II, Wi0 + (size_t)u * NOUT * II,
            h0hi, h0lo, RR, Wh0 + (size_t)u * NOUT * RR,
            pre0);
        cell0_k<<<cell_blocks, 256>>>(bi0 + (size_t)u * NOUT, bh0 + (size_t)u * NOUT);

        gemm_tc<<<gg, 256, SMEM_TOTAL>>>(
            h0hi, h0lo, RR, Wi1 + (size_t)u * NOUT * RR,
            h1hi, h1lo, RR, Wh1 + (size_t)u * NOUT * RR,
            pre1);
        cell1_k<<<cell_blocks, 256>>>(bi1 + (size_t)u * NOUT, bh1 + (size_t)u * NOUT, out, u);
    }
}